// round 12
// baseline (speedup 1.0000x reference)
#include <cuda_runtime.h>
#include <cstdint>

// HMM forward filter — DUAL-BATCH per warp-pair. CTA = 64 threads = 2 warps,
// handling 2 batches (A,B). Warp q owns output states i in [32q,32q+32) for
// BOTH batches; lane carries vA_i and vB_i. The two independent recurrences
// interleave inside the warp's instruction stream, hiding each other's
// LDS/bar/chain latency. TTp registers (T columns) are shared by both.
// One __syncthreads per iteration covers both batches' t-exchanges.
// Per batch step (R7 scheme, lagged shadow norm):
//   chain:  t_i=v_i*lik ; STS ; bar ; 16x LDS.128 ; 32x fma2 ; tree ;
//           v_i = out_i * f_scale (pow2 from s_total(k-1), exact)
//   shadow: half-sum shfl butterfly -> smem ; step-(k-1) outputs with exact r.
// T row-stochastic => sum(t@T)=sum(t): one sum normalizes est and pred.

#define Bn 256
#define Hn 2048
#define Sn 64
#define UD 4

using u64 = unsigned long long;

__device__ __forceinline__ u64 fma2(u64 a, u64 b, u64 c) {
    u64 d; asm("fma.rn.f32x2 %0, %1, %2, %3;" : "=l"(d) : "l"(a), "l"(b), "l"(c)); return d;
}
__device__ __forceinline__ u64 add2(u64 a, u64 b) {
    u64 d; asm("add.rn.f32x2 %0, %1, %2;" : "=l"(d) : "l"(a), "l"(b)); return d;
}
__device__ __forceinline__ u64 pack2(float lo, float hi) {
    u64 d; asm("mov.b64 %0, {%1, %2};" : "=l"(d) : "f"(lo), "f"(hi)); return d;
}
__device__ __forceinline__ void unpack2(u64 a, float& x, float& y) {
    asm("mov.b64 {%0, %1}, %2;" : "=f"(x), "=f"(y) : "l"(a));
}
__device__ __forceinline__ float fast_rcp(float s) {
    float r; asm("rcp.approx.f32 %0, %1;" : "=f"(r) : "f"(s)); return r;
}

// matvec over one batch's published t-buffer: 16 LDS.128 + 32 fma2 + tree
__device__ __forceinline__ float matvec64(const float* tb, const u64* TTp) {
    u64 a0 = 0, a1 = 0, a2 = 0, a3 = 0, a4 = 0, a5 = 0, a6 = 0, a7 = 0;
    const ulonglong2* tv = reinterpret_cast<const ulonglong2*>(tb);
#pragma unroll
    for (int t4 = 0; t4 < 16; t4 += 4) {
        ulonglong2 w0 = tv[t4 + 0];
        ulonglong2 w1 = tv[t4 + 1];
        ulonglong2 w2 = tv[t4 + 2];
        ulonglong2 w3 = tv[t4 + 3];
        a0 = fma2(w0.x, TTp[2 * t4 + 0], a0);
        a1 = fma2(w0.y, TTp[2 * t4 + 1], a1);
        a2 = fma2(w1.x, TTp[2 * t4 + 2], a2);
        a3 = fma2(w1.y, TTp[2 * t4 + 3], a3);
        a4 = fma2(w2.x, TTp[2 * t4 + 4], a4);
        a5 = fma2(w2.y, TTp[2 * t4 + 5], a5);
        a6 = fma2(w3.x, TTp[2 * t4 + 6], a6);
        a7 = fma2(w3.y, TTp[2 * t4 + 7], a7);
    }
    const u64 s2 = add2(add2(add2(a0, a1), add2(a2, a3)),
                        add2(add2(a4, a5), add2(a6, a7)));
    float sx, sy; unpack2(s2, sx, sy);
    return sx + sy;
}

__global__ void __launch_bounds__(64, 1) hmm_forward_kernel(
    const float* __restrict__ lik,    // [B, H, S]
    const float* __restrict__ init_s, // [S]
    const float* __restrict__ Tm,     // [S, S] row-major
    float* __restrict__ est_out,      // [B, H, S]
    float* __restrict__ pred_out)     // [B, H, S]
{
    __shared__ alignas(16) float tbuf[2][2][Sn];  // [batch][parity][state]
    __shared__ float ssum[2][2][2];               // [batch][parity][half]

    const int tid = threadIdx.x;
    const int q   = tid >> 5;          // output half
    const int p   = tid & 31;
    const int i   = 32 * q + p;        // owned state
    const int bA  = blockIdx.x * 2;
    const int bB  = bA + 1;

    // T column i as input pairs (shared by both batches)
    u64 TTp[32];
#pragma unroll
    for (int m = 0; m < 32; m++)
        TTp[m] = pack2(Tm[(2 * m) * Sn + i], Tm[(2 * m + 1) * Sn + i]);

    const float* likA = lik + (size_t)bA * Hn * Sn + i;
    const float* likB = lik + (size_t)bB * Hn * Sn + i;
    float* eoA = est_out  + (size_t)bA * Hn * Sn + i;
    float* poA = pred_out + (size_t)bA * Hn * Sn + i;
    float* eoB = est_out  + (size_t)bB * Hn * Sn + i;
    float* poB = pred_out + (size_t)bB * Hn * Sn + i;

    // ---- pred0 = init @ T (identical for every batch: compute once) ----
    tbuf[0][1][i] = init_s[i];
    __syncthreads();
    const float v0 = matvec64(tbuf[0][1], TTp);
    float vA = v0, vB = v0;
    __syncthreads();

    // ---- lik FIFOs ----
    float fifoA[UD], fifoB[UD];
#pragma unroll
    for (int j = 0; j < UD; j++) {
        fifoA[j] = likA[(size_t)j * Sn];
        fifoB[j] = likB[(size_t)j * Sn];
    }

    float fsA = 1.0f, fsB = 1.0f;          // pred0 sums to 1
    float tpA = 0.f, opA = 0.f, smA = 0.f;
    float tpB = 0.f, opB = 0.f, smB = 0.f;

    for (int kk = 0; kk < Hn; kk += UD) {
#pragma unroll
        for (int j = 0; j < UD; j++) {
            const int k = kk + j;
            const float lkA = fifoA[j];
            const float lkB = fifoB[j];
            int kn = k + UD; if (kn > Hn - 1) kn = Hn - 1;
            fifoA[j] = likA[(size_t)kn * Sn];
            fifoB[j] = likB[(size_t)kn * Sn];

            // ---- chain heads: publish both batches' t under one bar ----
            const float tA = vA * lkA;
            const float tB = vB * lkB;
            tbuf[0][k & 1][i] = tA;
            tbuf[1][k & 1][i] = tB;
            __syncthreads();

            // ---- shadow: finish step k-1 for both batches ----
            if (k > 0) {
                float sAt = smA + ssum[0][(k - 1) & 1][1 - q];
                float sBt = smB + ssum[1][(k - 1) & 1][1 - q];
                sAt = fmaxf(sAt, 1e-35f);
                sBt = fmaxf(sBt, 1e-35f);
                const float rA = fast_rcp(sAt);
                const float rB = fast_rcp(sBt);
                eoA[(size_t)(k - 1) * Sn] = tpA * rA;
                poA[(size_t)(k - 1) * Sn] = opA * rA;
                eoB[(size_t)(k - 1) * Sn] = tpB * rB;
                poB[(size_t)(k - 1) * Sn] = opB * rB;
                const unsigned ebA = (__float_as_uint(sAt) >> 23) & 0xFFu;
                const unsigned ebB = (__float_as_uint(sBt) >> 23) & 0xFFu;
                fsA = __uint_as_float((254u - ebA) << 23);   // exact 2^(127-e)
                fsB = __uint_as_float((254u - ebB) << 23);
            }

            // ---- chains: the two matvecs interleave in-warp ----
            const float outA = matvec64(tbuf[0][k & 1], TTp);
            const float outB = matvec64(tbuf[1][k & 1], TTp);
            vA = outA * fsA;
            vB = outB * fsB;

            // ---- shadow: half-sums for step k (latency hidden by peer batch) ----
            float sa = tA, sb = tB;
#pragma unroll
            for (int o = 16; o; o >>= 1) {
                sa += __shfl_xor_sync(0xFFFFFFFFu, sa, o);
                sb += __shfl_xor_sync(0xFFFFFFFFu, sb, o);
            }
            if (p == 0) { ssum[0][k & 1][q] = sa; ssum[1][k & 1][q] = sb; }
            smA = sa; smB = sb;
            tpA = tA; opA = outA;
            tpB = tB; opB = outB;
        }
    }

    // ---- flush last step ----
    __syncthreads();
    {
        float sAt = fmaxf(smA + ssum[0][(Hn - 1) & 1][1 - q], 1e-35f);
        float sBt = fmaxf(smB + ssum[1][(Hn - 1) & 1][1 - q], 1e-35f);
        const float rA = fast_rcp(sAt);
        const float rB = fast_rcp(sBt);
        eoA[(size_t)(Hn - 1) * Sn] = tpA * rA;
        poA[(size_t)(Hn - 1) * Sn] = opA * rA;
        eoB[(size_t)(Hn - 1) * Sn] = tpB * rB;
        poB[(size_t)(Hn - 1) * Sn] = opB * rB;
    }
}

extern "C" void kernel_launch(void* const* d_in, const int* in_sizes, int n_in,
                              void* d_out, int out_size) {
    const float* lik    = (const float*)d_in[0];   // [256, 2048, 64]
    const float* init_s = (const float*)d_in[1];   // [64]
    const float* Tm     = (const float*)d_in[2];   // [64, 64]
    float* eo = (float*)d_out;                      // est_traj first
    float* po = eo + (size_t)Bn * Hn * Sn;          // pred_traj second

    hmm_forward_kernel<<<Bn / 2, 64>>>(lik, init_s, Tm, eo, po);
}

// round 17
// speedup vs baseline: 1.6690x; 1.6690x over previous
#include <cuda_runtime.h>
#include <cstdint>

// HMM forward filter — R7 layout (2 warps/batch, 2 batches per 128-thread CTA,
// grid=128, 1 warp/SMSP, ONE plain bar.sync per step) with LAG-2 SUM
// PUBLICATION + DEADBEAT POW2 RESCALE.
// The 5-shfl butterfly for step k runs at the end of body k and is published
// at the head of body k+2, so its ~130cyc latency never blocks the barrier.
// Outputs for step k are written during body k+2 with exact r(k)=1/s_tot(k).
// v-rescale: g(k) = -eb(s(k-2)) - g(k-1) - g(k-2)  (integer log2 scales) gives
// a deadbeat exponent controller: log2 sum(v) settles to l(k)+l(k-1), bounded
// (naive lag-2 feedback a(k+1)=a(k)-a(k-2) is unstable, |roots|~1.15 -> NaN).
// All rescales are exact powers of two; outputs are same-frame ratios t/Σt.
// T row-stochastic => sum(t@T)=sum(t): one sum normalizes est and pred.

#define Bn 256
#define Hn 2048
#define Sn 64
#define UD 8
#define BATCHES_PER_CTA 2

using u64 = unsigned long long;

__device__ __forceinline__ u64 fma2(u64 a, u64 b, u64 c) {
    u64 d; asm("fma.rn.f32x2 %0, %1, %2, %3;" : "=l"(d) : "l"(a), "l"(b), "l"(c)); return d;
}
__device__ __forceinline__ u64 add2(u64 a, u64 b) {
    u64 d; asm("add.rn.f32x2 %0, %1, %2;" : "=l"(d) : "l"(a), "l"(b)); return d;
}
__device__ __forceinline__ u64 pack2(float lo, float hi) {
    u64 d; asm("mov.b64 %0, {%1, %2};" : "=l"(d) : "f"(lo), "f"(hi)); return d;
}
__device__ __forceinline__ void unpack2(u64 a, float& x, float& y) {
    asm("mov.b64 {%0, %1}, %2;" : "=f"(x), "=f"(y) : "l"(a));
}
__device__ __forceinline__ float fast_rcp(float s) {
    float r; asm("rcp.approx.f32 %0, %1;" : "=f"(r) : "f"(s)); return r;
}
template <int ID>
__device__ __forceinline__ void bar_imm() {
    asm volatile("bar.sync %0, 64;" :: "n"(ID) : "memory");
}
__device__ __forceinline__ void bar_batch(int lb) {
    if (lb == 0) bar_imm<1>(); else bar_imm<2>();
}

__global__ void __launch_bounds__(64 * BATCHES_PER_CTA, 1) hmm_forward_kernel(
    const float* __restrict__ lik,    // [B, H, S]
    const float* __restrict__ init_s, // [S]
    const float* __restrict__ Tm,     // [S, S] row-major
    float* __restrict__ est_out,      // [B, H, S]
    float* __restrict__ pred_out)     // [B, H, S]
{
    __shared__ alignas(16) float tbuf[BATCHES_PER_CTA][2][Sn];  // [batch][parity][state]
    __shared__ float ssum[BATCHES_PER_CTA][2][2];               // [batch][parity][half]

    const int tid = threadIdx.x;
    const int lb  = tid >> 6;          // local batch 0/1
    const int bt  = tid & 63;
    const int q   = bt >> 5;           // output half
    const int p   = bt & 31;
    const int i   = 32 * q + p;        // owned state
    const int b   = blockIdx.x * BATCHES_PER_CTA + lb;

    // T column i as input pairs: TTp[m] = {T[2m][i], T[2m+1][i]}
    u64 TTp[32];
#pragma unroll
    for (int m = 0; m < 32; m++)
        TTp[m] = pack2(Tm[(2 * m) * Sn + i], Tm[(2 * m + 1) * Sn + i]);

    const float* likp = lik + (size_t)b * Hn * Sn + i;
    float* eo = est_out  + (size_t)b * Hn * Sn + i;
    float* po = pred_out + (size_t)b * Hn * Sn + i;

    // ---- v = pred0 = init @ T (stage init in parity-1 buffer) ----
    tbuf[lb][1][i] = init_s[i];
    __syncthreads();
    float v;
    {
        const ulonglong2* tv = reinterpret_cast<const ulonglong2*>(tbuf[lb][1]);
        u64 a0 = 0, a1 = 0;
#pragma unroll
        for (int t = 0; t < 16; t++) {
            ulonglong2 w = tv[t];
            a0 = fma2(w.x, TTp[2 * t + 0], a0);
            a1 = fma2(w.y, TTp[2 * t + 1], a1);
        }
        u64 s2 = add2(a0, a1);
        float sx, sy; unpack2(s2, sx, sy);
        v = sx + sy;
    }
    __syncthreads();

    // ---- lik FIFO ----
    float fifo[UD];
#pragma unroll
    for (int j = 0; j < UD; j++)
        fifo[j] = likp[(size_t)j * Sn];

    // lag-2 pipelines: pipe0 = step k-1, pipe1 = step k-2
    float s_pipe0 = 0.f, s_pipe1 = 0.f;
    float t_m1 = 0.f, t_m2 = 0.f;
    float o_m1 = 0.f, o_m2 = 0.f;
    int   ge1 = 0, ge2 = 0;            // g(k-1), g(k-2): applied log2 scales

    for (int kk = 0; kk < Hn; kk += UD) {
#pragma unroll
        for (int j = 0; j < UD; j++) {
            const int k = kk + j;
            const float lk = fifo[j];

            // ---- chain head: t = v*lik ; publish t ; publish lagged s(k-2) ----
            const float t = v * lk;
            tbuf[lb][k & 1][i] = t;
            if (p == 0) ssum[lb][k & 1][q] = s_pipe1;   // s(k-2): long ready
            bar_batch(lb);

            // ---- FIFO refill (latency spans the step) ----
            int kn = k + UD; if (kn > Hn - 1) kn = Hn - 1;
            fifo[j] = likp[(size_t)kn * Sn];

            // ---- shadow: s_tot(k-2) -> r, deadbeat pow2 factor g(k) ----
            float f_scale = 1.0f, r = 0.f;
            int g = 0;
            if (k >= 2) {
                float s_tot = s_pipe1 + ssum[lb][k & 1][1 - q];
                s_tot = fmaxf(s_tot, 1e-35f);
                r = fast_rcp(s_tot);
                const int eb = (int)((__float_as_uint(s_tot) >> 23) & 0xFFu) - 127;
                g = -eb - ge1 - ge2;                     // deadbeat controller
                g = max(-126, min(127, g));
                f_scale = __uint_as_float((unsigned)(g + 127) << 23);  // exact 2^g
            }

            // ---- chain: out_i = sum_j t_j T[j][i] ----
            u64 a0 = 0, a1 = 0, a2 = 0, a3 = 0, a4 = 0, a5 = 0, a6 = 0, a7 = 0;
            const ulonglong2* tv = reinterpret_cast<const ulonglong2*>(tbuf[lb][k & 1]);
#pragma unroll
            for (int t4 = 0; t4 < 16; t4 += 4) {
                ulonglong2 w0 = tv[t4 + 0];
                ulonglong2 w1 = tv[t4 + 1];
                ulonglong2 w2 = tv[t4 + 2];
                ulonglong2 w3 = tv[t4 + 3];
                a0 = fma2(w0.x, TTp[2 * t4 + 0], a0);
                a1 = fma2(w0.y, TTp[2 * t4 + 1], a1);
                a2 = fma2(w1.x, TTp[2 * t4 + 2], a2);
                a3 = fma2(w1.y, TTp[2 * t4 + 3], a3);
                a4 = fma2(w2.x, TTp[2 * t4 + 4], a4);
                a5 = fma2(w2.y, TTp[2 * t4 + 5], a5);
                a6 = fma2(w3.x, TTp[2 * t4 + 6], a6);
                a7 = fma2(w3.y, TTp[2 * t4 + 7], a7);
            }
            const u64 s2 = add2(add2(add2(a0, a1), add2(a2, a3)),
                                add2(add2(a4, a5), add2(a6, a7)));
            float sx, sy; unpack2(s2, sx, sy);
            const float out = sx + sy;

            // chain tail: exact pow2 rescale (factor from lagged shadow)
            v = out * f_scale;

            // ---- shadow: write step k-2 outputs with exact r(k-2) ----
            if (k >= 2) {
                eo[(size_t)(k - 2) * Sn] = t_m2 * r;
                po[(size_t)(k - 2) * Sn] = o_m2 * r;
            }

            // ---- shadow: butterfly for step k (latency spans 2 steps) ----
            float sm = t;
#pragma unroll
            for (int o = 16; o; o >>= 1) sm += __shfl_xor_sync(0xFFFFFFFFu, sm, o);

            // rotate lag pipelines
            s_pipe1 = s_pipe0;  s_pipe0 = sm;
            t_m2 = t_m1;        t_m1 = t;
            o_m2 = o_m1;        o_m1 = out;
            ge2 = ge1;          ge1 = g;
        }
    }

    // ---- flush last two steps ----
    if (p == 0) {
        ssum[lb][(Hn - 2) & 1][q] = s_pipe1;
        ssum[lb][(Hn - 1) & 1][q] = s_pipe0;
    }
    __syncthreads();
    {
        float sA = fmaxf(s_pipe1 + ssum[lb][(Hn - 2) & 1][1 - q], 1e-35f);
        float sB = fmaxf(s_pipe0 + ssum[lb][(Hn - 1) & 1][1 - q], 1e-35f);
        const float rA = fast_rcp(sA);
        const float rB = fast_rcp(sB);
        eo[(size_t)(Hn - 2) * Sn] = t_m2 * rA;
        po[(size_t)(Hn - 2) * Sn] = o_m2 * rA;
        eo[(size_t)(Hn - 1) * Sn] = t_m1 * rB;
        po[(size_t)(Hn - 1) * Sn] = o_m1 * rB;
    }
}

extern "C" void kernel_launch(void* const* d_in, const int* in_sizes, int n_in,
                              void* d_out, int out_size) {
    const float* lik    = (const float*)d_in[0];   // [256, 2048, 64]
    const float* init_s = (const float*)d_in[1];   // [64]
    const float* Tm     = (const float*)d_in[2];   // [64, 64]
    float* eo = (float*)d_out;                      // est_traj first
    float* po = eo + (size_t)Bn * Hn * Sn;          // pred_traj second

    hmm_forward_kernel<<<Bn / BATCHES_PER_CTA, 64 * BATCHES_PER_CTA>>>(lik, init_s, Tm, eo, po);
}